// round 17
// baseline (speedup 1.0000x reference)
#include <cuda_runtime.h>
#include <cuda_bf16.h>
#include <cuda_fp16.h>
#include <math.h>
#include <stdint.h>

#define BATCH 2
#define SEQ 2048
#define DMODEL 1024
#define DINNER 2048
#define DSTATE 16
#define DTRANK 64
#define DXL 96           // DT_RANK + 2*D_STATE
#define NROWS (BATCH*SEQ) // 4096
#define KSPLIT 4

// ---------------- fp32 scratch ----------------
__device__ float g_xdbl[(size_t)NROWS * DXL];
__device__ float g_part[(size_t)KSPLIT * NROWS * DXL];
__device__ float g_delta[(size_t)NROWS * DINNER];

// ---------------- fp16 scratch ----------------
__device__ __half g_xz_h[(size_t)NROWS * 2 * DINNER];
__device__ __half g_hs_hi[(size_t)NROWS * DMODEL];
__device__ __half g_inw_hi[(size_t)2 * DINNER * DMODEL];
__device__ __half g_u_hi[(size_t)NROWS * DINNER];
__device__ __half g_u_lo[(size_t)NROWS * DINNER];
__device__ __half g_xpw_hi[(size_t)128 * DINNER];
__device__ __half g_dt_hi[(size_t)NROWS * DTRANK];
__device__ __half g_dt_lo[(size_t)NROWS * DTRANK];
__device__ __half g_dtw_hi[(size_t)DINNER * DTRANK];
__device__ __half g_y_hi[(size_t)NROWS * DINNER];
__device__ __half g_outw_hi[(size_t)DMODEL * DINNER];

// ---------------- helpers ----------------
__device__ __forceinline__ uint32_t smem_u32(const void* p) {
    uint32_t a;
    asm("{ .reg .u64 t; cvta.to.shared.u64 t, %1; cvt.u32.u64 %0, t; }" : "=r"(a) : "l"(p));
    return a;
}
__device__ __forceinline__ void split_fp16(float v, __half& h, __half& l) {
    h = __float2half(v);
    l = __float2half(v - __half2float(h));
}
__device__ __forceinline__ void store_hi4(__half* hi, int idx4, float4 v) {
    *(__half2*)(hi + idx4)     = __halves2half2(__float2half(v.x), __float2half(v.y));
    *(__half2*)(hi + idx4 + 2) = __halves2half2(__float2half(v.z), __float2half(v.w));
}
__device__ __forceinline__ float4 load_h4(const __half* p) {
    uint2 raw = *(const uint2*)p;
    __half2 a = *(__half2*)&raw.x, b = *(__half2*)&raw.y;
    return make_float4(__low2float(a), __high2float(a), __low2float(b), __high2float(b));
}

// ---------------- fused input conversion ----------------
#define Q_HS   1048576
#define Q_INW  (Q_HS + 1048576)
#define Q_XPW  (Q_INW + 65536)
#define Q_DTW  (Q_XPW + 32768)
#define Q_OUTW (Q_DTW + 524288)
#define CVT_BLOCKS (Q_OUTW / 256)

__global__ void cvt_all_kernel(const float* __restrict__ hs, const float* __restrict__ inw,
                               const float* __restrict__ xpw, const float* __restrict__ dtw,
                               const float* __restrict__ outw,
                               __half* __restrict__ hs_hi, __half* __restrict__ inw_hi,
                               __half* __restrict__ xpw_hi, __half* __restrict__ dtw_hi,
                               __half* __restrict__ outw_hi) {
    int q = blockIdx.x * blockDim.x + threadIdx.x;
    if (q < Q_HS) {
        int idx4 = q * 4;
        store_hi4(hs_hi, idx4, *(const float4*)(hs + idx4));
    } else if (q < Q_INW) {
        int idx4 = (q - Q_HS) * 4;
        store_hi4(inw_hi, idx4, *(const float4*)(inw + idx4));
    } else if (q < Q_XPW) {
        int idx4 = (q - Q_INW) * 4;
        int r = idx4 >> 11;
        float4 v = (r < DXL) ? *(const float4*)(xpw + idx4) : make_float4(0.f, 0.f, 0.f, 0.f);
        store_hi4(xpw_hi, idx4, v);
    } else if (q < Q_DTW) {
        int idx4 = (q - Q_XPW) * 4;
        store_hi4(dtw_hi, idx4, *(const float4*)(dtw + idx4));
    } else {
        int idx4 = (q - Q_DTW) * 4;
        store_hi4(outw_hi, idx4, *(const float4*)(outw + idx4));
    }
}

#define MMA_OP(ACC, AF, BF) \
    asm volatile("mma.sync.aligned.m16n8k16.row.col.f32.f16.f16.f32 " \
                 "{%0,%1,%2,%3}, {%4,%5,%6,%7}, {%8,%9}, {%0,%1,%2,%3};" \
                 : "+f"((ACC)[0]), "+f"((ACC)[1]), "+f"((ACC)[2]), "+f"((ACC)[3]) \
                 : "r"((AF)[0]), "r"((AF)[1]), "r"((AF)[2]), "r"((AF)[3]), \
                   "r"((BF)[0]), "r"((BF)[1]))

#define LDSM_X4(R0, R1, R2, R3, ADDR) \
    asm volatile("ldmatrix.sync.aligned.m8n8.x4.shared.b16 {%0,%1,%2,%3}, [%4];" \
                 : "=r"(R0), "=r"(R1), "=r"(R2), "=r"(R3) : "r"(ADDR))

// ======== BIG 1-pass GEMM: 128 thr, 2x2 warps, 64x64 warp tile, K-chunk 64 ====
#define RSB 72
#define BTILE_BYTES (128 * RSB * 2)      // 18432
#define BIG_SMEM (3 * 2 * BTILE_BYTES)   // 110592

template <int HALF_OUT>
__global__ __launch_bounds__(128, 2)
void gemm_big(const __half* __restrict__ Ahi, const __half* __restrict__ Bhi,
              float* __restrict__ Cf, __half* __restrict__ Ch, int K, int ldc) {
    extern __shared__ char smem[];
    const uint32_t sb = smem_u32(smem);
    const int tid = threadIdx.x;
    const int wid = tid >> 5, lane = tid & 31;
    const int warp_m = wid >> 1, warp_n = wid & 1;
    const int bm = blockIdx.y * 128, bn = blockIdx.x * 128;
    const int NC = K >> 6;
    constexpr uint32_t SBYTES = 2 * BTILE_BYTES;

    uint32_t offA[4], offB[4];
    {
        const int arow = lane & 15;
        const int acol = (lane >> 4) << 3;
#pragma unroll
        for (int mi = 0; mi < 4; mi++)
            offA[mi] = (uint32_t)((warp_m * 64 + mi * 16 + arow) * (RSB * 2) + acol * 2);
        const int bcol = ((lane >> 3) & 1) << 3;
#pragma unroll
        for (int p = 0; p < 4; p++) {
            int r = warp_n * 64 + p * 16 + ((lane >> 4) << 3) + (lane & 7);
            offB[p] = (uint32_t)(r * (RSB * 2) + bcol * 2);
        }
    }

    float acc[4][8][4];
#pragma unroll
    for (int i = 0; i < 4; i++)
#pragma unroll
        for (int j = 0; j < 8; j++)
#pragma unroll
            for (int q = 0; q < 4; q++) acc[i][j][q] = 0.f;

    auto load_stage = [&](int c, uint32_t sbase) {
        size_t k0 = (size_t)c * 64;
#pragma unroll
        for (int it = 0; it < 16; it++) {
            int t = tid + it * 128;
            int tile = t >> 10;
            int s = t & 1023;
            int row = s >> 3, seg = s & 7;
            const char* src = (tile == 0)
                ? (const char*)(Ahi + (size_t)(bm + row) * K + k0) + seg * 16
                : (const char*)(Bhi + (size_t)(bn + row) * K + k0) + seg * 16;
            uint32_t dst = sbase + (uint32_t)(tile * BTILE_BYTES + row * (RSB * 2) + seg * 16);
            asm volatile("cp.async.cg.shared.global [%0], [%1], 16;" :: "r"(dst), "l"(src) : "memory");
        }
        asm volatile("cp.async.commit_group;" ::: "memory");
    };

    load_stage(0, sb);
    if (NC > 1) load_stage(1, sb + SBYTES);
    int buf = 0;
    for (int c = 0; c < NC; c++) {
        if (c + 1 < NC) { asm volatile("cp.async.wait_group 1;" ::: "memory"); }
        else            { asm volatile("cp.async.wait_group 0;" ::: "memory"); }
        __syncthreads();
        if (c + 2 < NC) {
            int wb = buf + 2; if (wb >= 3) wb -= 3;
            load_stage(c + 2, sb + (uint32_t)wb * SBYTES);
        }
        uint32_t sbase = sb + (uint32_t)buf * SBYTES;
        const uint32_t aB = sbase, bB = sbase + BTILE_BYTES;
#pragma unroll
        for (int ks = 0; ks < 4; ks++) {
            const uint32_t kb = (uint32_t)(ks * 32);
            uint32_t aH[4][4], bH[8][2];
#pragma unroll
            for (int mi = 0; mi < 4; mi++)
                LDSM_X4(aH[mi][0], aH[mi][1], aH[mi][2], aH[mi][3], aB + offA[mi] + kb);
#pragma unroll
            for (int p = 0; p < 4; p++)
                LDSM_X4(bH[2*p][0], bH[2*p][1], bH[2*p+1][0], bH[2*p+1][1], bB + offB[p] + kb);
#pragma unroll
            for (int mi = 0; mi < 4; mi++)
#pragma unroll
                for (int ni = 0; ni < 8; ni++) MMA_OP(acc[mi][ni], aH[mi], bH[ni]);
        }
        if (++buf == 3) buf = 0;
    }

    // ---- epilogue ----
#pragma unroll
    for (int mi = 0; mi < 4; mi++) {
        int row0 = bm + warp_m * 64 + mi * 16 + (lane >> 2);
#pragma unroll
        for (int ni = 0; ni < 8; ni++) {
            int col0 = bn + warp_n * 64 + ni * 8 + ((lane & 3) << 1);
#pragma unroll
            for (int half = 0; half < 2; half++) {
                int r = row0 + half * 8;
                float v0 = acc[mi][ni][half * 2 + 0];
                float v1 = acc[mi][ni][half * 2 + 1];
                if (HALF_OUT) {
                    *(__half2*)(Ch + (size_t)r * ldc + col0) =
                        __halves2half2(__float2half(v0), __float2half(v1));
                } else {
                    *(float2*)(Cf + (size_t)r * ldc + col0) = make_float2(v0, v1);
                }
            }
        }
    }
}

// ======== small GEMM (2-pass), 256 thr, warp tile 64x32, 2-stage ========
#define RS 40
#define TILE_BYTES (128 * RS * 2)      // 10240
#define SMEM_P2 (2 * 3 * TILE_BYTES)   // 61440

template <int EPI>
__global__ __launch_bounds__(256, 2)
void gemm_mma(const __half* __restrict__ Ahi, const __half* __restrict__ Alo,
              const __half* __restrict__ Bhi,
              float* __restrict__ C, const float* __restrict__ bias,
              int K, int ldc, int Nvalid, int Kloop, size_t partStride) {
    extern __shared__ char smem[];
    const uint32_t sb = smem_u32(smem);
    const int tid = threadIdx.x;
    const int wid = tid >> 5, lane = tid & 31;
    const int warp_m = wid >> 2, warp_n = wid & 3;
    const int bm = blockIdx.y * 128, bn = blockIdx.x * 128;
    const int koff = blockIdx.z * Kloop;
    const int NC = Kloop >> 5;
    constexpr uint32_t SBYTES = 3 * TILE_BYTES;

    uint32_t offA[4], offB[2];
    {
        const int arow = lane & 15;
        const int acol = (lane >> 4) << 3;
#pragma unroll
        for (int mi = 0; mi < 4; mi++)
            offA[mi] = (uint32_t)((warp_m * 64 + mi * 16 + arow) * (RS * 2) + acol * 2);
        const int bcol = ((lane >> 3) & 1) << 3;
#pragma unroll
        for (int p = 0; p < 2; p++) {
            int r = warp_n * 32 + p * 16 + ((lane >> 4) << 3) + (lane & 7);
            offB[p] = (uint32_t)(r * (RS * 2) + bcol * 2);
        }
    }

    float acc[4][4][4];
#pragma unroll
    for (int i = 0; i < 4; i++)
#pragma unroll
        for (int j = 0; j < 4; j++)
#pragma unroll
            for (int q = 0; q < 4; q++) acc[i][j][q] = 0.f;

    auto load_stage = [&](int c, uint32_t sbase) {
        size_t k0 = (size_t)koff + (size_t)c * 32;
#pragma unroll
        for (int it = 0; it < 6; it++) {
            int t = tid + it * 256;
            int tile = t >> 9;
            int s = t & 511;
            int row = s >> 2, seg = s & 3;
            const char* src;
            if (tile == 0)      src = (const char*)(Ahi + (size_t)(bm + row) * K + k0) + seg * 16;
            else if (tile == 1) src = (const char*)(Alo + (size_t)(bm + row) * K + k0) + seg * 16;
            else                src = (const char*)(Bhi + (size_t)(bn + row) * K + k0) + seg * 16;
            uint32_t dst = sbase + (uint32_t)(tile * TILE_BYTES + row * (RS * 2) + seg * 16);
            asm volatile("cp.async.cg.shared.global [%0], [%1], 16;" :: "r"(dst), "l"(src) : "memory");
        }
        asm volatile("cp.async.commit_group;" ::: "memory");
    };

    load_stage(0, sb);
    for (int c = 0; c < NC; c++) {
        if (c + 1 < NC) {
            load_stage(c + 1, sb + (uint32_t)((c + 1) & 1) * SBYTES);
            asm volatile("cp.async.wait_group 1;" ::: "memory");
        } else {
            asm volatile("cp.async.wait_group 0;" ::: "memory");
        }
        __syncthreads();
        uint32_t sbase = sb + (uint32_t)(c & 1) * SBYTES;
        const uint32_t aHiB = sbase, aLoB = sbase + TILE_BYTES, bHiB = sbase + 2 * TILE_BYTES;
#pragma unroll
        for (int ks = 0; ks < 2; ks++) {
            const uint32_t kb = (uint32_t)(ks * 32);
            uint32_t aH[4][4], bH[4][2];
#pragma unroll
            for (int mi = 0; mi < 4; mi++)
                LDSM_X4(aH[mi][0], aH[mi][1], aH[mi][2], aH[mi][3], aHiB + offA[mi] + kb);
#pragma unroll
            for (int p = 0; p < 2; p++)
                LDSM_X4(bH[2*p][0], bH[2*p][1], bH[2*p+1][0], bH[2*p+1][1], bHiB + offB[p] + kb);
            uint32_t aL[4][4];
#pragma unroll
            for (int mi = 0; mi < 4; mi++)
                LDSM_X4(aL[mi][0], aL[mi][1], aL[mi][2], aL[mi][3], aLoB + offA[mi] + kb);
#pragma unroll
            for (int mi = 0; mi < 4; mi++)
#pragma unroll
                for (int ni = 0; ni < 4; ni++) MMA_OP(acc[mi][ni], aH[mi], bH[ni]);
#pragma unroll
            for (int mi = 0; mi < 4; mi++)
#pragma unroll
                for (int ni = 0; ni < 4; ni++) MMA_OP(acc[mi][ni], aL[mi], bH[ni]);
        }
        __syncthreads();
    }

    float* Cz = C + partStride * blockIdx.z;
#pragma unroll
    for (int mi = 0; mi < 4; mi++) {
        int row0 = bm + warp_m * 64 + mi * 16 + (lane >> 2);
#pragma unroll
        for (int ni = 0; ni < 4; ni++) {
            int col0 = bn + warp_n * 32 + ni * 8 + ((lane & 3) << 1);
            if (col0 < Nvalid) {
#pragma unroll
                for (int half = 0; half < 2; half++) {
                    int r = row0 + half * 8;
                    float v0 = acc[mi][ni][half * 2 + 0];
                    float v1 = acc[mi][ni][half * 2 + 1];
                    if (EPI == 1) {
                        v0 += bias[col0];
                        v1 += bias[col0 + 1];
                        v0 = (v0 > 20.f) ? v0 : __logf(1.f + __expf(v0));
                        v1 = (v1 > 20.f) ? v1 : __logf(1.f + __expf(v1));
                    }
                    *(float2*)(Cz + (size_t)r * ldc + col0) = make_float2(v0, v1);
                }
            }
        }
    }
}

// ---------------- conv + SiLU, fp16 in, fp16 hi/lo out, 4 ch/thread ----------
__global__ void conv_silu_kernel(const __half* __restrict__ xz_h,
                                 const float* __restrict__ w,
                                 const float* __restrict__ bias,
                                 __half* __restrict__ u_hi,
                                 __half* __restrict__ u_lo) {
    int q = blockIdx.x * blockDim.x + threadIdx.x;
    if (q >= NROWS * DINNER / 4) return;
    int cg = q % (DINNER / 4);
    int row = q / (DINNER / 4);
    int t = row % SEQ;
    int b = row / SEQ;
    int c4 = cg * 4;
    int idx4 = q * 4;

    float4 bv = *(const float4*)(bias + c4);
    float acc[4] = { bv.x, bv.y, bv.z, bv.w };
    float4 wr[4];
#pragma unroll
    for (int j = 0; j < 4; j++) wr[j] = *(const float4*)(w + (c4 + j) * 4);

#pragma unroll
    for (int k = 0; k < 4; k++) {
        int tt = t - 3 + k;
        if (tt >= 0) {
            float4 xv = load_h4(xz_h + ((size_t)(b * SEQ + tt)) * (2 * DINNER) + c4);
            acc[0] += xv.x * ((const float*)&wr[0])[k];
            acc[1] += xv.y * ((const float*)&wr[1])[k];
            acc[2] += xv.z * ((const float*)&wr[2])[k];
            acc[3] += xv.w * ((const float*)&wr[3])[k];
        }
    }
    __half h[4], l[4];
#pragma unroll
    for (int j = 0; j < 4; j++) {
        float v = acc[j] / (1.f + __expf(-acc[j]));
        split_fp16(v, h[j], l[j]);
    }
    *(__half2*)(u_hi + idx4)     = __halves2half2(h[0], h[1]);
    *(__half2*)(u_hi + idx4 + 2) = __halves2half2(h[2], h[3]);
    *(__half2*)(u_lo + idx4)     = __halves2half2(l[0], l[1]);
    *(__half2*)(u_lo + idx4 + 2) = __halves2half2(l[2], l[3]);
}

// ---------------- split-K reduce for x_proj + dt split ----------------
__global__ void reduce_xdbl_kernel(const float* __restrict__ part,
                                   float* __restrict__ xdbl,
                                   __half* __restrict__ dt_hi,
                                   __half* __restrict__ dt_lo) {
    int idx = blockIdx.x * blockDim.x + threadIdx.x;
    if (idx >= NROWS * DXL) return;
    float v = 0.f;
#pragma unroll
    for (int z = 0; z < KSPLIT; z++) v += part[(size_t)z * NROWS * DXL + idx];
    xdbl[idx] = v;
    int c = idx % DXL;
    if (c < DTRANK) {
        int r = idx / DXL;
        __half h, l;
        split_fp16(v, h, l);
        dt_hi[r * DTRANK + c] = h;
        dt_lo[r * DTRANK + c] = l;
    }
}

// ---------------- selective scan: 4 states/lane, 32 ch/block ----------------
#define SCAN_T 64
#define SCAN_CH 32
__global__ __launch_bounds__(128, 4)
void scan_kernel(const float* __restrict__ delta,
                 const float* __restrict__ xdbl,
                 const __half* __restrict__ u_hi,
                 const __half* __restrict__ xz_h,
                 const float* __restrict__ A_log,
                 const float* __restrict__ Dp,
                 __half* __restrict__ y_hi) {
    __shared__ __align__(16) float s_d[SCAN_T][SCAN_CH];
    __shared__ __align__(16) float s_u[SCAN_T][SCAN_CH];
    __shared__ __align__(16) float s_z[SCAN_T][SCAN_CH];
    __shared__ __align__(16) float s_B[SCAN_T][DSTATE];
    __shared__ __align__(16) float s_C[SCAN_T][DSTATE];

    const int b = blockIdx.y;
    const int d0 = blockIdx.x * SCAN_CH;
    const int tid = threadIdx.x;
    const int ch = tid >> 2;
    const int q  = tid & 3;
    const int d  = d0 + ch;

    float4 Al = *(const float4*)(A_log + d * DSTATE + q * 4);
    const float A0 = -__expf(Al.x), A1 = -__expf(Al.y), A2 = -__expf(Al.z), A3 = -__expf(Al.w);
    const float Dreg = Dp[d];
    float h0 = 0.f, h1 = 0.f, h2 = 0.f, h3 = 0.f;

    for (int t0 = 0; t0 < SEQ; t0 += SCAN_T) {
#pragma unroll
        for (int rep = 0; rep < 4; rep++) {
            int i = tid + rep * 128;
            int tt = i >> 3, cc = (i & 7) * 4;
            size_t base = (size_t)(b * SEQ + t0 + tt);
            *(float4*)&s_d[tt][cc] = *(const float4*)(delta + base * DINNER + d0 + cc);
            *(float4*)&s_u[tt][cc] = load_h4(u_hi + base * DINNER + d0 + cc);
            *(float4*)&s_z[tt][cc] = load_h4(xz_h + base * (2 * DINNER) + DINNER + d0 + cc);
        }
#pragma unroll
        for (int rep = 0; rep < 2; rep++) {
            int i = tid + rep * 128;
            int tt = i >> 2, cc = (i & 3) * 4;
            size_t base = (size_t)(b * SEQ + t0 + tt);
            *(float4*)&s_B[tt][cc] = *(const float4*)(xdbl + base * DXL + DTRANK + cc);
            *(float4*)&s_C[tt][cc] = *(const float4*)(xdbl + base * DXL + DTRANK + DSTATE + cc);
        }
        __syncthreads();

#pragma unroll 2
        for (int tt = 0; tt < SCAN_T; tt++) {
            float dt = s_d[tt][ch];
            float ut = s_u[tt][ch];
            float4 Bv = *(const float4*)&s_B[tt][q * 4];
            float4 Cv = *(const float4*)&s_C[tt][q * 4];
            float dtu = dt * ut;
            h0 = __expf(dt * A0) * h0 + dtu * Bv.x;
            h1 = __expf(dt * A1) * h1 + dtu * Bv.y;
            h2 = __expf(dt * A2) * h2 + dtu * Bv.z;
            h3 = __expf(dt * A3) * h3 + dtu * Bv.w;
            float part = h0 * Cv.x + h1 * Cv.y + h2 * Cv.z + h3 * Cv.w;
            part += __shfl_xor_sync(0xFFFFFFFFu, part, 1);
            part += __shfl_xor_sync(0xFFFFFFFFu, part, 2);
            if (q == 0) {
                float yv = part + ut * Dreg;
                float z = s_z[tt][ch];
                yv *= z / (1.f + __expf(-z));
                y_hi[((size_t)(b * SEQ + t0 + tt)) * DINNER + d] = __float2half(yv);
            }
        }
        __syncthreads();
    }
}

// ---------------- launch -------------------------------------------------------
extern "C" void kernel_launch(void* const* d_in, const int* in_sizes, int n_in,
                              void* d_out, int out_size) {
    const float* hs    = (const float*)d_in[0];
    const float* inw   = (const float*)d_in[1];
    const float* convw = (const float*)d_in[2];
    const float* convb = (const float*)d_in[3];
    const float* xpw   = (const float*)d_in[4];
    const float* dtw   = (const float*)d_in[5];
    const float* dtb   = (const float*)d_in[6];
    const float* alog  = (const float*)d_in[7];
    const float* Dp    = (const float*)d_in[8];
    const float* outw  = (const float*)d_in[9];
    float* out = (float*)d_out;

    float *xdbl, *part, *delta;
    cudaGetSymbolAddress((void**)&xdbl,  g_xdbl);
    cudaGetSymbolAddress((void**)&part,  g_part);
    cudaGetSymbolAddress((void**)&delta, g_delta);

    __half *xz_h, *hs_hi, *inw_hi, *u_hi, *u_lo, *xpw_hi, *dt_hi, *dt_lo, *dtw_hi, *y_hi, *outw_hi;
    cudaGetSymbolAddress((void**)&xz_h,   g_xz_h);
    cudaGetSymbolAddress((void**)&hs_hi,  g_hs_hi);
    cudaGetSymbolAddress((void**)&inw_hi, g_inw_hi);
    cudaGetSymbolAddress((void**)&u_hi,   g_u_hi);    cudaGetSymbolAddress((void**)&u_lo,   g_u_lo);
    cudaGetSymbolAddress((void**)&xpw_hi, g_xpw_hi);
    cudaGetSymbolAddress((void**)&dt_hi,  g_dt_hi);   cudaGetSymbolAddress((void**)&dt_lo,  g_dt_lo);
    cudaGetSymbolAddress((void**)&dtw_hi, g_dtw_hi);
    cudaGetSymbolAddress((void**)&y_hi,   g_y_hi);
    cudaGetSymbolAddress((void**)&outw_hi,g_outw_hi);

    cudaFuncSetAttribute((const void*)gemm_big<0>, cudaFuncAttributeMaxDynamicSharedMemorySize, BIG_SMEM);
    cudaFuncSetAttribute((const void*)gemm_big<1>, cudaFuncAttributeMaxDynamicSharedMemorySize, BIG_SMEM);
    cudaFuncSetAttribute((const void*)gemm_mma<0>, cudaFuncAttributeMaxDynamicSharedMemorySize, SMEM_P2);
    cudaFuncSetAttribute((const void*)gemm_mma<1>, cudaFuncAttributeMaxDynamicSharedMemorySize, SMEM_P2);

    const int CT = 256;
    // ---- all input conversions in one kernel ----
    cvt_all_kernel<<<CVT_BLOCKS, CT>>>(hs, inw, xpw, dtw, outw,
                                       hs_hi, inw_hi, xpw_hi, dtw_hi, outw_hi);
    // ---- in_proj (1-pass, K-chunk 64, fp16 output) ----
    gemm_big<1><<<dim3(32, 32), 128, BIG_SMEM>>>(hs_hi, inw_hi, nullptr, xz_h, DMODEL, 2 * DINNER);
    // ---- conv + silu (fp16 in/out) ----
    conv_silu_kernel<<<(NROWS * DINNER / 4 + CT - 1) / CT, CT>>>(xz_h, convw, convb, u_hi, u_lo);
    // ---- x_proj: split-K=4 (2-pass) ----
    gemm_mma<0><<<dim3(1, 32, KSPLIT), 256, SMEM_P2>>>(u_hi, u_lo, xpw_hi,
                                                       part, nullptr, DINNER, DXL, DXL,
                                                       DINNER / KSPLIT, (size_t)NROWS * DXL);
    reduce_xdbl_kernel<<<(NROWS * DXL + CT - 1) / CT, CT>>>(part, xdbl, dt_hi, dt_lo);
    // ---- dt_proj + softplus (2-pass) ----
    gemm_mma<1><<<dim3(16, 32), 256, SMEM_P2>>>(dt_hi, dt_lo, dtw_hi,
                                                delta, dtb, DTRANK, DINNER, DINNER, DTRANK, 0);
    // ---- selective scan ----
    scan_kernel<<<dim3(DINNER / SCAN_CH, BATCH), 128>>>(delta, xdbl, u_hi, xz_h, alog, Dp, y_hi);
    // ---- out_proj (1-pass, K-chunk 64, fp32 output) ----
    gemm_big<0><<<dim3(8, 32), 128, BIG_SMEM>>>(y_hi, outw_hi, out, nullptr, DINNER, DMODEL);
}